// round 8
// baseline (speedup 1.0000x reference)
#include <cuda_runtime.h>
#include <cuda_bf16.h>
#include <math.h>
#include <stdint.h>

#define T_TOK 4096
#define HID   1024
#define FFN   2816
#define NE    8
#define RMAX  (T_TOK * 2)
#define BM    192
#define BN    64
#define BK    16
#define NTHR  384
#define MT_MAX 56
#define AS    200   // sA[k][m] row stride in floats; 200 mod 32 == 8 -> banks 8k+m conflict-free
#define BS    72    // sB[k][n] row stride; 72 mod 32 == 8

// ---------------- device scratch (allocation-free: __device__ globals) ----------------
__device__ float g_xn[T_TOK * HID];          // normalized activations, fp32
__device__ float g_act[RMAX * FFN];          // SwiGLU activations, fp32 (~92MB)
__device__ int   g_counts[NE];
__device__ int   g_perm[RMAX];               // routed row -> token
__device__ float g_gate[RMAX];               // routed row -> gate prob
__device__ int   g_topi[T_TOK * 2];
__device__ float g_topp[T_TOK * 2];
__device__ int   g_tile_e[MT_MAX];
__device__ int   g_tile_row0[MT_MAX];
__device__ int   g_tile_rows[MT_MAX];
__device__ int   g_nmt;

// ---------------- helpers ----------------
__device__ __forceinline__ unsigned f2tf(float x) {
    unsigned u;
    asm("cvt.rna.tf32.f32 %0, %1;" : "=r"(u) : "f"(x));
    return u;
}

__device__ __forceinline__ void mma_tf32(float c[4], const unsigned a[4], const unsigned b[2]) {
    asm volatile(
        "mma.sync.aligned.m16n8k8.row.col.f32.tf32.tf32.f32 "
        "{%0,%1,%2,%3}, {%4,%5,%6,%7}, {%8,%9}, {%0,%1,%2,%3};"
        : "+f"(c[0]), "+f"(c[1]), "+f"(c[2]), "+f"(c[3])
        : "r"(a[0]), "r"(a[1]), "r"(a[2]), "r"(a[3]), "r"(b[0]), "r"(b[1]));
}

// ---------------- kernel 0: zero output + counts ----------------
__global__ void k_zero(float* __restrict__ out, int n) {
    int gi = blockIdx.x * blockDim.x + threadIdx.x;
    for (int i = gi; i < n; i += gridDim.x * blockDim.x) out[i] = 0.0f;
    if (gi < NE) g_counts[gi] = 0;
}

// ---------------- kernel 1: RMSNorm + router + top2 ----------------
__global__ void k_rms_router(const float* __restrict__ x,
                             const float* __restrict__ lnw,
                             const float* __restrict__ rw) {
    int t = blockIdx.x;
    int tid = threadIdx.x;
    int lane = tid & 31, w = tid >> 5;
    int h0 = tid * 8;

    const float* xr = x + (size_t)t * HID;
    float4 v0 = *(const float4*)(xr + h0);
    float4 v1 = *(const float4*)(xr + h0 + 4);

    float ss = v0.x * v0.x + v0.y * v0.y + v0.z * v0.z + v0.w * v0.w +
               v1.x * v1.x + v1.y * v1.y + v1.z * v1.z + v1.w * v1.w;
#pragma unroll
    for (int o = 16; o; o >>= 1) ss += __shfl_xor_sync(0xffffffffu, ss, o);

    __shared__ float s_red[4];
    __shared__ float s_l[4][8];
    __shared__ float s_rstd;
    if (lane == 0) s_red[w] = ss;
    __syncthreads();
    if (tid == 0) {
        float tot = s_red[0] + s_red[1] + s_red[2] + s_red[3];
        s_rstd = rsqrtf(tot / (float)HID + 1e-5f);
    }
    __syncthreads();
    float rstd = s_rstd;

    float4 wa = *(const float4*)(lnw + h0);
    float4 wb = *(const float4*)(lnw + h0 + 4);
    float xn[8];
    xn[0] = v0.x * rstd * wa.x;  xn[1] = v0.y * rstd * wa.y;
    xn[2] = v0.z * rstd * wa.z;  xn[3] = v0.w * rstd * wa.w;
    xn[4] = v1.x * rstd * wb.x;  xn[5] = v1.y * rstd * wb.y;
    xn[6] = v1.z * rstd * wb.z;  xn[7] = v1.w * rstd * wb.w;

    *(float4*)(g_xn + (size_t)t * HID + h0)     = make_float4(xn[0], xn[1], xn[2], xn[3]);
    *(float4*)(g_xn + (size_t)t * HID + h0 + 4) = make_float4(xn[4], xn[5], xn[6], xn[7]);

    float l[8] = {0, 0, 0, 0, 0, 0, 0, 0};
#pragma unroll
    for (int j = 0; j < 8; j++) {
        const float4* rp = (const float4*)(rw + (size_t)(h0 + j) * NE);
        float4 r0 = rp[0], r1 = rp[1];
        float xv = xn[j];
        l[0] += xv * r0.x; l[1] += xv * r0.y; l[2] += xv * r0.z; l[3] += xv * r0.w;
        l[4] += xv * r1.x; l[5] += xv * r1.y; l[6] += xv * r1.z; l[7] += xv * r1.w;
    }
#pragma unroll
    for (int o = 16; o; o >>= 1) {
#pragma unroll
        for (int e = 0; e < 8; e++) l[e] += __shfl_xor_sync(0xffffffffu, l[e], o);
    }
    if (lane == 0) {
#pragma unroll
        for (int e = 0; e < 8; e++) s_l[w][e] = l[e];
    }
    __syncthreads();
    if (tid == 0) {
        float lg[8];
#pragma unroll
        for (int e = 0; e < 8; e++) lg[e] = s_l[0][e] + s_l[1][e] + s_l[2][e] + s_l[3][e];
        float mx = lg[0];
#pragma unroll
        for (int e = 1; e < 8; e++) mx = fmaxf(mx, lg[e]);
        float p[8]; float se = 0.0f;
#pragma unroll
        for (int e = 0; e < 8; e++) { p[e] = expf(lg[e] - mx); se += p[e]; }
        float inv = 1.0f / se;
        int i1 = 0;
#pragma unroll
        for (int e = 1; e < 8; e++) if (p[e] > p[i1]) i1 = e;
        int i2 = -1;
#pragma unroll
        for (int e = 0; e < 8; e++) if (e != i1 && (i2 < 0 || p[e] > p[i2])) i2 = e;
        g_topi[2 * t + 0] = i1; g_topp[2 * t + 0] = p[i1] * inv;
        g_topi[2 * t + 1] = i2; g_topp[2 * t + 1] = p[i2] * inv;
        atomicAdd(&g_counts[i1], 1);
        atomicAdd(&g_counts[i2], 1);
    }
}

// ---------------- kernel 2: offsets + scatter + tile map (single block) ----------------
__global__ void k_route() {
    __shared__ int s_cur[NE];
    int tid = threadIdx.x;
    if (tid == 0) {
        int off = 0, nm = 0;
        for (int e = 0; e < NE; e++) {
            s_cur[e] = off;
            int n = g_counts[e];
            for (int m0 = 0; m0 < n; m0 += BM) {
                g_tile_e[nm] = e;
                g_tile_row0[nm] = off + m0;
                g_tile_rows[nm] = min(BM, n - m0);
                nm++;
            }
            off += n;
        }
        g_nmt = nm;
    }
    __syncthreads();
    for (int t = tid; t < T_TOK; t += blockDim.x) {
        for (int k = 0; k < 2; k++) {
            int e = g_topi[2 * t + k];
            int pos = atomicAdd(&s_cur[e], 1);
            g_perm[pos] = t;
            g_gate[pos] = g_topp[2 * t + k];
        }
    }
}

// ---------------- kernel 3: GEMM1 (X@W1, X@W3) + SiLU*mul ----------------
// BM=192, BN=64, 384 threads, 12 warps (6m x 2n), warp tile 32x32 per matrix.
__global__ __launch_bounds__(NTHR, 1) void k_gemm1(const float* __restrict__ w1,
                                                   const float* __restrict__ w3) {
    int mt = blockIdx.y;
    if (mt >= g_nmt) return;
    int e = g_tile_e[mt], row0 = g_tile_row0[mt], rows = g_tile_rows[mt];
    int n0 = blockIdx.x * BN;

    __shared__ __align__(16) unsigned sA[2][BK][AS];
    __shared__ __align__(16) unsigned sB1[2][BK][BS];
    __shared__ __align__(16) unsigned sB3[2][BK][BS];
    __shared__ int s_tok[BM];

    int tid = threadIdx.x;
    if (tid < BM) s_tok[tid] = (tid < rows) ? g_perm[row0 + tid] : -1;
    __syncthreads();

    // A loader: 384 threads cover 192 rows x 2 k-halves
    int am = tid >> 1;
    int ak = (tid & 1) * 8;
    int atok = s_tok[am];
    const float* ap = (atok >= 0) ? (g_xn + (size_t)atok * HID + ak) : nullptr;

    // B loader: first 256 threads cover 16k x 64n (float4), both w1 and w3
    bool bactive = tid < 256;
    int bk = tid >> 4;                 // 0..15 for tid<256
    int bc = (tid & 15) * 4;
    const float* w1p = w1 + (size_t)e * HID * FFN + (size_t)bk * FFN + n0 + bc;
    const float* w3p = w3 + (size_t)e * HID * FFN + (size_t)bk * FFN + n0 + bc;

    float4 ra0, ra1, rb1, rb3;
    auto ldg_stage = [&](int s) {
        int kg = s * BK;
        if (ap) {
            ra0 = *(const float4*)(ap + kg);
            ra1 = *(const float4*)(ap + kg + 4);
        } else {
            ra0 = make_float4(0, 0, 0, 0);
            ra1 = make_float4(0, 0, 0, 0);
        }
        if (bactive) {
            rb1 = *(const float4*)(w1p + (size_t)kg * FFN);
            rb3 = *(const float4*)(w3p + (size_t)kg * FFN);
        }
    };
    auto sts_stage = [&](int buf) {
        sA[buf][ak + 0][am] = f2tf(ra0.x);
        sA[buf][ak + 1][am] = f2tf(ra0.y);
        sA[buf][ak + 2][am] = f2tf(ra0.z);
        sA[buf][ak + 3][am] = f2tf(ra0.w);
        sA[buf][ak + 4][am] = f2tf(ra1.x);
        sA[buf][ak + 5][am] = f2tf(ra1.y);
        sA[buf][ak + 6][am] = f2tf(ra1.z);
        sA[buf][ak + 7][am] = f2tf(ra1.w);
        if (bactive) {
            *(uint4*)&sB1[buf][bk][bc] = make_uint4(f2tf(rb1.x), f2tf(rb1.y), f2tf(rb1.z), f2tf(rb1.w));
            *(uint4*)&sB3[buf][bk][bc] = make_uint4(f2tf(rb3.x), f2tf(rb3.y), f2tf(rb3.z), f2tf(rb3.w));
        }
    };

    int lane = tid & 31, wz = tid >> 5;
    int mw = (wz >> 1) * 32;   // 6 m-warps cover 192 rows
    int nw = (wz & 1) * 32;    // 2 n-warps cover 64 cols
    int g = lane >> 2, tg = lane & 3;

    float acc1[2][4][4] = {};
    float acc3[2][4][4] = {};

    ldg_stage(0);
    sts_stage(0);
    __syncthreads();

    const int NS = HID / BK;  // 64
    for (int s = 0; s < NS; s++) {
        int buf = s & 1;
        if (s + 1 < NS) ldg_stage(s + 1);
#pragma unroll
        for (int kk = 0; kk < BK; kk += 8) {
            unsigned a[2][4], b1[4][2], b3[4][2];
#pragma unroll
            for (int i = 0; i < 2; i++) {
                int m = mw + i * 16;
                a[i][0] = sA[buf][kk + tg][m + g];
                a[i][1] = sA[buf][kk + tg][m + g + 8];
                a[i][2] = sA[buf][kk + tg + 4][m + g];
                a[i][3] = sA[buf][kk + tg + 4][m + g + 8];
            }
#pragma unroll
            for (int j = 0; j < 4; j++) {
                int n = nw + j * 8 + g;
                b1[j][0] = sB1[buf][kk + tg][n];
                b1[j][1] = sB1[buf][kk + tg + 4][n];
                b3[j][0] = sB3[buf][kk + tg][n];
                b3[j][1] = sB3[buf][kk + tg + 4][n];
            }
#pragma unroll
            for (int i = 0; i < 2; i++)
#pragma unroll
                for (int j = 0; j < 4; j++) {
                    mma_tf32(acc1[i][j], a[i], b1[j]);
                    mma_tf32(acc3[i][j], a[i], b3[j]);
                }
        }
        if (s + 1 < NS) sts_stage((s + 1) & 1);
        __syncthreads();
    }

    // epilogue: act = silu(h1) * h3
#pragma unroll
    for (int i = 0; i < 2; i++) {
        int rb = mw + i * 16 + g;
#pragma unroll
        for (int j = 0; j < 4; j++) {
            int c = nw + j * 8 + tg * 2;
            if (rb < rows) {
                float h1a = acc1[i][j][0], h1b = acc1[i][j][1];
                float h3a = acc3[i][j][0], h3b = acc3[i][j][1];
                float sa = h1a / (1.0f + __expf(-h1a));
                float sb = h1b / (1.0f + __expf(-h1b));
                *(float2*)(g_act + (size_t)(row0 + rb) * FFN + n0 + c) = make_float2(sa * h3a, sb * h3b);
            }
            int rb2 = rb + 8;
            if (rb2 < rows) {
                float h1a = acc1[i][j][2], h1b = acc1[i][j][3];
                float h3a = acc3[i][j][2], h3b = acc3[i][j][3];
                float sa = h1a / (1.0f + __expf(-h1a));
                float sb = h1b / (1.0f + __expf(-h1b));
                *(float2*)(g_act + (size_t)(row0 + rb2) * FFN + n0 + c) = make_float2(sa * h3a, sb * h3b);
            }
        }
    }
}

// ---------------- kernel 4: GEMM2 (act @ W2), gated scatter-add into out ----------------
// BM=192, BN=64, 384 threads, 12 warps (6m x 2n), warp tile 32x32.
__global__ __launch_bounds__(NTHR, 1) void k_gemm2(const float* __restrict__ w2,
                                                   float* __restrict__ out) {
    int mt = blockIdx.y;
    if (mt >= g_nmt) return;
    int e = g_tile_e[mt], row0 = g_tile_row0[mt], rows = g_tile_rows[mt];
    int n0 = blockIdx.x * BN;

    __shared__ __align__(16) unsigned sA[2][BK][AS];
    __shared__ __align__(16) unsigned sB[2][BK][BS];
    __shared__ int   s_tok[BM];
    __shared__ float s_g[BM];

    int tid = threadIdx.x;
    if (tid < BM) {
        bool v = tid < rows;
        s_tok[tid] = v ? g_perm[row0 + tid] : -1;
        s_g[tid]   = v ? g_gate[row0 + tid] : 0.0f;
    }
    __syncthreads();

    int am = tid >> 1;
    int ak = (tid & 1) * 8;
    bool avalid = am < rows;
    const float* ap = g_act + (size_t)(row0 + am) * FFN + ak;

    bool bactive = tid < 256;
    int bk = tid >> 4;
    int bc = (tid & 15) * 4;
    const float* bp = w2 + (size_t)e * FFN * HID + (size_t)bk * HID + n0 + bc;

    float4 ra0, ra1, rb;
    auto ldg_stage = [&](int s) {
        int kg = s * BK;
        if (avalid) {
            ra0 = *(const float4*)(ap + kg);
            ra1 = *(const float4*)(ap + kg + 4);
        } else {
            ra0 = make_float4(0, 0, 0, 0);
            ra1 = make_float4(0, 0, 0, 0);
        }
        if (bactive) rb = *(const float4*)(bp + (size_t)kg * HID);
    };
    auto sts_stage = [&](int buf) {
        sA[buf][ak + 0][am] = f2tf(ra0.x);
        sA[buf][ak + 1][am] = f2tf(ra0.y);
        sA[buf][ak + 2][am] = f2tf(ra0.z);
        sA[buf][ak + 3][am] = f2tf(ra0.w);
        sA[buf][ak + 4][am] = f2tf(ra1.x);
        sA[buf][ak + 5][am] = f2tf(ra1.y);
        sA[buf][ak + 6][am] = f2tf(ra1.z);
        sA[buf][ak + 7][am] = f2tf(ra1.w);
        if (bactive)
            *(uint4*)&sB[buf][bk][bc] = make_uint4(f2tf(rb.x), f2tf(rb.y), f2tf(rb.z), f2tf(rb.w));
    };

    int lane = tid & 31, wz = tid >> 5;
    int mw = (wz >> 1) * 32;
    int nw = (wz & 1) * 32;
    int g = lane >> 2, tg = lane & 3;

    float acc[2][4][4] = {};

    ldg_stage(0);
    sts_stage(0);
    __syncthreads();

    const int NS = FFN / BK;  // 176
    for (int s = 0; s < NS; s++) {
        int buf = s & 1;
        if (s + 1 < NS) ldg_stage(s + 1);
#pragma unroll
        for (int kk = 0; kk < BK; kk += 8) {
            unsigned a[2][4], b[4][2];
#pragma unroll
            for (int i = 0; i < 2; i++) {
                int m = mw + i * 16;
                a[i][0] = sA[buf][kk + tg][m + g];
                a[i][1] = sA[buf][kk + tg][m + g + 8];
                a[i][2] = sA[buf][kk + tg + 4][m + g];
                a[i][3] = sA[buf][kk + tg + 4][m + g + 8];
            }
#pragma unroll
            for (int j = 0; j < 4; j++) {
                int n = nw + j * 8 + g;
                b[j][0] = sB[buf][kk + tg][n];
                b[j][1] = sB[buf][kk + tg + 4][n];
            }
#pragma unroll
            for (int i = 0; i < 2; i++)
#pragma unroll
                for (int j = 0; j < 4; j++) mma_tf32(acc[i][j], a[i], b[j]);
        }
        if (s + 1 < NS) sts_stage((s + 1) & 1);
        __syncthreads();
    }

    // epilogue: out[token] += gate * y (exactly 2 contributions per element -> deterministic)
#pragma unroll
    for (int i = 0; i < 2; i++) {
        int rb0 = mw + i * 16 + g;
#pragma unroll
        for (int j = 0; j < 4; j++) {
            int c = nw + j * 8 + tg * 2;
            if (rb0 < rows) {
                int tk = s_tok[rb0];
                float gg = s_g[rb0];
                atomicAdd(&out[(size_t)tk * HID + n0 + c], gg * acc[i][j][0]);
                atomicAdd(&out[(size_t)tk * HID + n0 + c + 1], gg * acc[i][j][1]);
            }
            int rb2 = rb0 + 8;
            if (rb2 < rows) {
                int tk = s_tok[rb2];
                float gg = s_g[rb2];
                atomicAdd(&out[(size_t)tk * HID + n0 + c], gg * acc[i][j][2]);
                atomicAdd(&out[(size_t)tk * HID + n0 + c + 1], gg * acc[i][j][3]);
            }
        }
    }
}

// ---------------- launch ----------------
extern "C" void kernel_launch(void* const* d_in, const int* in_sizes, int n_in,
                              void* d_out, int out_size) {
    const float* hs  = (const float*)d_in[0];  // hidden_states [2,2048,1024]
    const float* lnw = (const float*)d_in[1];  // ln_weight [1024]
    const float* rw  = (const float*)d_in[2];  // router_w [1024,8]
    const float* w1  = (const float*)d_in[3];  // [8,1024,2816]
    const float* w3  = (const float*)d_in[4];  // [8,1024,2816]
    const float* w2  = (const float*)d_in[5];  // [8,2816,1024]
    float* out = (float*)d_out;                // [2,2048,1024] fp32

    k_zero<<<2048, 256>>>(out, out_size);
    k_rms_router<<<T_TOK, 128>>>(hs, lnw, rw);
    k_route<<<1, 256>>>();
    dim3 g1(FFN / BN, MT_MAX);
    k_gemm1<<<g1, NTHR>>>(w1, w3);
    dim3 g2(HID / BN, MT_MAX);
    k_gemm2<<<g2, NTHR>>>(w2, out);
}

// round 10
// speedup vs baseline: 1.1694x; 1.1694x over previous
#include <cuda_runtime.h>
#include <cuda_bf16.h>
#include <math.h>
#include <stdint.h>

#define T_TOK 4096
#define HID   1024
#define FFN   2816
#define NE    8
#define RMAX  (T_TOK * 2)
#define BM    128
#define BN    64
#define BK    16
#define MT_MAX 80

// packed SMEM geometry (uint2 units). Element (kb, tg, m/n): pair {v(kb*8+tg), v(kb*8+tg+4)}
#define A_TGS 132           // tg stride (m-dim 128 + pad): 2*132 mod 32 = 8
#define A_KBS 536           // kb stride: 2*536 mod 32 = 16
#define A_BUF 1072          // per-buffer size (uint2)
#define B_TGS 68            // n-dim 64 + pad: 2*68 mod 32 = 8
#define B_KBS 280           // 2*280 mod 32 = 16
#define B_BUF 560

// ---------------- device scratch (allocation-free: __device__ globals) ----------------
__device__ float g_xn[T_TOK * HID];          // normalized activations, fp32
__device__ float g_act[RMAX * FFN];          // SwiGLU activations, fp32 (~92MB)
__device__ int   g_counts[NE];
__device__ int   g_perm[RMAX];               // routed row -> token
__device__ float g_gate[RMAX];               // routed row -> gate prob
__device__ int   g_topi[T_TOK * 2];
__device__ float g_topp[T_TOK * 2];
__device__ int   g_tile_e[MT_MAX];
__device__ int   g_tile_row0[MT_MAX];
__device__ int   g_tile_rows[MT_MAX];
__device__ int   g_nmt;

// ---------------- helpers ----------------
__device__ __forceinline__ unsigned f2tf(float x) {
    unsigned u;
    asm("cvt.rna.tf32.f32 %0, %1;" : "=r"(u) : "f"(x));
    return u;
}

__device__ __forceinline__ void mma_tf32(float c[4], const unsigned a[4], const unsigned b[2]) {
    asm volatile(
        "mma.sync.aligned.m16n8k8.row.col.f32.tf32.tf32.f32 "
        "{%0,%1,%2,%3}, {%4,%5,%6,%7}, {%8,%9}, {%0,%1,%2,%3};"
        : "+f"(c[0]), "+f"(c[1]), "+f"(c[2]), "+f"(c[3])
        : "r"(a[0]), "r"(a[1]), "r"(a[2]), "r"(a[3]), "r"(b[0]), "r"(b[1]));
}

// ---------------- kernel 0: zero output + counts ----------------
__global__ void k_zero(float* __restrict__ out, int n) {
    int gi = blockIdx.x * blockDim.x + threadIdx.x;
    for (int i = gi; i < n; i += gridDim.x * blockDim.x) out[i] = 0.0f;
    if (gi < NE) g_counts[gi] = 0;
}

// ---------------- kernel 1: RMSNorm + router + top2 ----------------
__global__ void k_rms_router(const float* __restrict__ x,
                             const float* __restrict__ lnw,
                             const float* __restrict__ rw) {
    int t = blockIdx.x;
    int tid = threadIdx.x;
    int lane = tid & 31, w = tid >> 5;
    int h0 = tid * 8;

    const float* xr = x + (size_t)t * HID;
    float4 v0 = *(const float4*)(xr + h0);
    float4 v1 = *(const float4*)(xr + h0 + 4);

    float ss = v0.x * v0.x + v0.y * v0.y + v0.z * v0.z + v0.w * v0.w +
               v1.x * v1.x + v1.y * v1.y + v1.z * v1.z + v1.w * v1.w;
#pragma unroll
    for (int o = 16; o; o >>= 1) ss += __shfl_xor_sync(0xffffffffu, ss, o);

    __shared__ float s_red[4];
    __shared__ float s_l[4][8];
    __shared__ float s_rstd;
    if (lane == 0) s_red[w] = ss;
    __syncthreads();
    if (tid == 0) {
        float tot = s_red[0] + s_red[1] + s_red[2] + s_red[3];
        s_rstd = rsqrtf(tot / (float)HID + 1e-5f);
    }
    __syncthreads();
    float rstd = s_rstd;

    float4 wa = *(const float4*)(lnw + h0);
    float4 wb = *(const float4*)(lnw + h0 + 4);
    float xn[8];
    xn[0] = v0.x * rstd * wa.x;  xn[1] = v0.y * rstd * wa.y;
    xn[2] = v0.z * rstd * wa.z;  xn[3] = v0.w * rstd * wa.w;
    xn[4] = v1.x * rstd * wb.x;  xn[5] = v1.y * rstd * wb.y;
    xn[6] = v1.z * rstd * wb.z;  xn[7] = v1.w * rstd * wb.w;

    *(float4*)(g_xn + (size_t)t * HID + h0)     = make_float4(xn[0], xn[1], xn[2], xn[3]);
    *(float4*)(g_xn + (size_t)t * HID + h0 + 4) = make_float4(xn[4], xn[5], xn[6], xn[7]);

    float l[8] = {0, 0, 0, 0, 0, 0, 0, 0};
#pragma unroll
    for (int j = 0; j < 8; j++) {
        const float4* rp = (const float4*)(rw + (size_t)(h0 + j) * NE);
        float4 r0 = rp[0], r1 = rp[1];
        float xv = xn[j];
        l[0] += xv * r0.x; l[1] += xv * r0.y; l[2] += xv * r0.z; l[3] += xv * r0.w;
        l[4] += xv * r1.x; l[5] += xv * r1.y; l[6] += xv * r1.z; l[7] += xv * r1.w;
    }
#pragma unroll
    for (int o = 16; o; o >>= 1) {
#pragma unroll
        for (int e = 0; e < 8; e++) l[e] += __shfl_xor_sync(0xffffffffu, l[e], o);
    }
    if (lane == 0) {
#pragma unroll
        for (int e = 0; e < 8; e++) s_l[w][e] = l[e];
    }
    __syncthreads();
    if (tid == 0) {
        float lg[8];
#pragma unroll
        for (int e = 0; e < 8; e++) lg[e] = s_l[0][e] + s_l[1][e] + s_l[2][e] + s_l[3][e];
        float mx = lg[0];
#pragma unroll
        for (int e = 1; e < 8; e++) mx = fmaxf(mx, lg[e]);
        float p[8]; float se = 0.0f;
#pragma unroll
        for (int e = 0; e < 8; e++) { p[e] = expf(lg[e] - mx); se += p[e]; }
        float inv = 1.0f / se;
        int i1 = 0;
#pragma unroll
        for (int e = 1; e < 8; e++) if (p[e] > p[i1]) i1 = e;
        int i2 = -1;
#pragma unroll
        for (int e = 0; e < 8; e++) if (e != i1 && (i2 < 0 || p[e] > p[i2])) i2 = e;
        g_topi[2 * t + 0] = i1; g_topp[2 * t + 0] = p[i1] * inv;
        g_topi[2 * t + 1] = i2; g_topp[2 * t + 1] = p[i2] * inv;
        atomicAdd(&g_counts[i1], 1);
        atomicAdd(&g_counts[i2], 1);
    }
}

// ---------------- kernel 2: offsets + scatter + tile map (single block) ----------------
__global__ void k_route() {
    __shared__ int s_cur[NE];
    int tid = threadIdx.x;
    if (tid == 0) {
        int off = 0, nm = 0;
        for (int e = 0; e < NE; e++) {
            s_cur[e] = off;
            int n = g_counts[e];
            for (int m0 = 0; m0 < n; m0 += BM) {
                g_tile_e[nm] = e;
                g_tile_row0[nm] = off + m0;
                g_tile_rows[nm] = min(BM, n - m0);
                nm++;
            }
            off += n;
        }
        g_nmt = nm;
    }
    __syncthreads();
    for (int t = tid; t < T_TOK; t += blockDim.x) {
        for (int k = 0; k < 2; k++) {
            int e = g_topi[2 * t + k];
            int pos = atomicAdd(&s_cur[e], 1);
            g_perm[pos] = t;
            g_gate[pos] = g_topp[2 * t + k];
        }
    }
}

// ---------------- kernel 3: GEMM1 (X@W1, X@W3) + SiLU*mul ----------------
// 2 CTAs/SM, paired-k uint2 SMEM (LDS.64 fragments), R5-style coalesced loaders.
__global__ __launch_bounds__(256, 2) void k_gemm1(const float* __restrict__ w1,
                                                  const float* __restrict__ w3) {
    int mt = blockIdx.y;
    if (mt >= g_nmt) return;
    int e = g_tile_e[mt], row0 = g_tile_row0[mt], rows = g_tile_rows[mt];
    int n0 = blockIdx.x * BN;

    __shared__ __align__(16) uint2 sA[2 * A_BUF];
    __shared__ __align__(16) uint2 sB1[2 * B_BUF];
    __shared__ __align__(16) uint2 sB3[2 * B_BUF];
    __shared__ int s_tok[BM];

    int tid = threadIdx.x;
    if (tid < BM) s_tok[tid] = (tid < rows) ? g_perm[row0 + tid] : -1;
    __syncthreads();

    // A loader: thread owns (row am, kb half); 2x float4 LDG, 4x STS.64 paired in-thread
    int am  = tid >> 1;
    int kbA = tid & 1;
    int atok = s_tok[am];
    const float* ap = (atok >= 0) ? (g_xn + (size_t)atok * HID + kbA * 8) : nullptr;

    // B loader: R5-style. thread owns (k-row bk, 4 cols bc); 1 float4 LDG per matrix.
    int bk = tid >> 4;                 // 0..15
    int bc = (tid & 15) * 4;           // 0..60 step 4
    const float* w1p = w1 + (size_t)e * HID * FFN + (size_t)bk * FFN + n0 + bc;
    const float* w3p = w3 + (size_t)e * HID * FFN + (size_t)bk * FFN + n0 + bc;
    // paired-cell decomposition of bk: pair (kb*8+tg, kb*8+tg+4); hi selects x/y half
    int kbB = bk >> 3, krem = bk & 7, tgB = krem & 3, hiB = (krem >> 2) & 1;
    // u32 word offset of this thread's first store (excluding buf and n term)
    int bwoff = kbB * (B_KBS * 2) + tgB * (B_TGS * 2) + hiB;

    float4 ra0, ra1, rb1, rb3;
    auto ldg_stage = [&](int s) {
        int kg = s * BK;
        if (ap) {
            ra0 = *(const float4*)(ap + kg);
            ra1 = *(const float4*)(ap + kg + 4);
        } else {
            ra0 = make_float4(0, 0, 0, 0);
            ra1 = make_float4(0, 0, 0, 0);
        }
        rb1 = *(const float4*)(w1p + (size_t)kg * FFN);
        rb3 = *(const float4*)(w3p + (size_t)kg * FFN);
    };
    auto sts_stage = [&](int buf) {
        uint2* pa = sA + buf * A_BUF + kbA * A_KBS + am;
        pa[0 * A_TGS] = make_uint2(f2tf(ra0.x), f2tf(ra1.x));
        pa[1 * A_TGS] = make_uint2(f2tf(ra0.y), f2tf(ra1.y));
        pa[2 * A_TGS] = make_uint2(f2tf(ra0.z), f2tf(ra1.z));
        pa[3 * A_TGS] = make_uint2(f2tf(ra0.w), f2tf(ra1.w));
        unsigned* pb1 = (unsigned*)sB1 + buf * (B_BUF * 2) + bwoff + bc * 2;
        pb1[0] = f2tf(rb1.x); pb1[2] = f2tf(rb1.y); pb1[4] = f2tf(rb1.z); pb1[6] = f2tf(rb1.w);
        unsigned* pb3 = (unsigned*)sB3 + buf * (B_BUF * 2) + bwoff + bc * 2;
        pb3[0] = f2tf(rb3.x); pb3[2] = f2tf(rb3.y); pb3[4] = f2tf(rb3.z); pb3[6] = f2tf(rb3.w);
    };

    int lane = tid & 31, wz = tid >> 5;
    int mw = (wz & 3) * 32;   // 4 m-warps cover 128 rows
    int nw = (wz >> 2) * 32;  // 2 n-warps cover 64 cols
    int g = lane >> 2, tg = lane & 3;

    float acc1[2][4][4] = {};
    float acc3[2][4][4] = {};

    ldg_stage(0);
    sts_stage(0);
    __syncthreads();

    const int NS = HID / BK;  // 64
    for (int s = 0; s < NS; s++) {
        int buf = s & 1;
        if (s + 1 < NS) ldg_stage(s + 1);
#pragma unroll
        for (int kb = 0; kb < 2; kb++) {
            const uint2* pa = sA + buf * A_BUF + kb * A_KBS + tg * A_TGS;
            uint2 a0[2], a1[2];
#pragma unroll
            for (int i = 0; i < 2; i++) {
                a0[i] = pa[mw + i * 16 + g];
                a1[i] = pa[mw + i * 16 + g + 8];
            }
            const uint2* pb1 = sB1 + buf * B_BUF + kb * B_KBS + tg * B_TGS + nw;
            const uint2* pb3 = sB3 + buf * B_BUF + kb * B_KBS + tg * B_TGS + nw;
#pragma unroll
            for (int j = 0; j < 4; j++) {
                uint2 b1 = pb1[j * 8 + g];
                uint2 b3 = pb3[j * 8 + g];
                unsigned bb1[2] = {b1.x, b1.y};
                unsigned bb3[2] = {b3.x, b3.y};
#pragma unroll
                for (int i = 0; i < 2; i++) {
                    unsigned aa[4] = {a0[i].x, a1[i].x, a0[i].y, a1[i].y};
                    mma_tf32(acc1[i][j], aa, bb1);
                    mma_tf32(acc3[i][j], aa, bb3);
                }
            }
        }
        if (s + 1 < NS) sts_stage((s + 1) & 1);
        __syncthreads();
    }

    // epilogue: act = silu(h1) * h3
#pragma unroll
    for (int i = 0; i < 2; i++) {
        int rb = mw + i * 16 + g;
#pragma unroll
        for (int j = 0; j < 4; j++) {
            int c = nw + j * 8 + tg * 2;
            if (rb < rows) {
                float h1a = acc1[i][j][0], h1b = acc1[i][j][1];
                float h3a = acc3[i][j][0], h3b = acc3[i][j][1];
                float sa = h1a / (1.0f + __expf(-h1a));
                float sb = h1b / (1.0f + __expf(-h1b));
                *(float2*)(g_act + (size_t)(row0 + rb) * FFN + n0 + c) = make_float2(sa * h3a, sb * h3b);
            }
            int rb2 = rb + 8;
            if (rb2 < rows) {
                float h1a = acc1[i][j][2], h1b = acc1[i][j][3];
                float h3a = acc3[i][j][2], h3b = acc3[i][j][3];
                float sa = h1a / (1.0f + __expf(-h1a));
                float sb = h1b / (1.0f + __expf(-h1b));
                *(float2*)(g_act + (size_t)(row0 + rb2) * FFN + n0 + c) = make_float2(sa * h3a, sb * h3b);
            }
        }
    }
}

// ---------------- kernel 4: GEMM2 (act @ W2), gated scatter-add into out ----------------
__global__ __launch_bounds__(256, 2) void k_gemm2(const float* __restrict__ w2,
                                                  float* __restrict__ out) {
    int mt = blockIdx.y;
    if (mt >= g_nmt) return;
    int e = g_tile_e[mt], row0 = g_tile_row0[mt], rows = g_tile_rows[mt];
    int n0 = blockIdx.x * BN;

    __shared__ __align__(16) uint2 sA[2 * A_BUF];
    __shared__ __align__(16) uint2 sB[2 * B_BUF];
    __shared__ int   s_tok[BM];
    __shared__ float s_g[BM];

    int tid = threadIdx.x;
    if (tid < BM) {
        bool v = tid < rows;
        s_tok[tid] = v ? g_perm[row0 + tid] : -1;
        s_g[tid]   = v ? g_gate[row0 + tid] : 0.0f;
    }
    __syncthreads();

    int am  = tid >> 1;
    int kbA = tid & 1;
    bool avalid = am < rows;
    const float* ap = g_act + (size_t)(row0 + am) * FFN + kbA * 8;

    int bk = tid >> 4;
    int bc = (tid & 15) * 4;
    const float* bp = w2 + (size_t)e * FFN * HID + (size_t)bk * HID + n0 + bc;
    int kbB = bk >> 3, krem = bk & 7, tgB = krem & 3, hiB = (krem >> 2) & 1;
    int bwoff = kbB * (B_KBS * 2) + tgB * (B_TGS * 2) + hiB;

    float4 ra0, ra1, rb;
    auto ldg_stage = [&](int s) {
        int kg = s * BK;
        if (avalid) {
            ra0 = *(const float4*)(ap + kg);
            ra1 = *(const float4*)(ap + kg + 4);
        } else {
            ra0 = make_float4(0, 0, 0, 0);
            ra1 = make_float4(0, 0, 0, 0);
        }
        rb = *(const float4*)(bp + (size_t)kg * HID);
    };
    auto sts_stage = [&](int buf) {
        uint2* pa = sA + buf * A_BUF + kbA * A_KBS + am;
        pa[0 * A_TGS] = make_uint2(f2tf(ra0.x), f2tf(ra1.x));
        pa[1 * A_TGS] = make_uint2(f2tf(ra0.y), f2tf(ra1.y));
        pa[2 * A_TGS] = make_uint2(f2tf(ra0.z), f2tf(ra1.z));
        pa[3 * A_TGS] = make_uint2(f2tf(ra0.w), f2tf(ra1.w));
        unsigned* pb = (unsigned*)sB + buf * (B_BUF * 2) + bwoff + bc * 2;
        pb[0] = f2tf(rb.x); pb[2] = f2tf(rb.y); pb[4] = f2tf(rb.z); pb[6] = f2tf(rb.w);
    };

    int lane = tid & 31, wz = tid >> 5;
    int mw = (wz & 3) * 32;
    int nw = (wz >> 2) * 32;
    int g = lane >> 2, tg = lane & 3;

    float acc[2][4][4] = {};

    ldg_stage(0);
    sts_stage(0);
    __syncthreads();

    const int NS = FFN / BK;  // 176
    for (int s = 0; s < NS; s++) {
        int buf = s & 1;
        if (s + 1 < NS) ldg_stage(s + 1);
#pragma unroll
        for (int kb = 0; kb < 2; kb++) {
            const uint2* pa = sA + buf * A_BUF + kb * A_KBS + tg * A_TGS;
            uint2 a0[2], a1[2];
#pragma unroll
            for (int i = 0; i < 2; i++) {
                a0[i] = pa[mw + i * 16 + g];
                a1[i] = pa[mw + i * 16 + g + 8];
            }
            const uint2* pb = sB + buf * B_BUF + kb * B_KBS + tg * B_TGS + nw;
#pragma unroll
            for (int j = 0; j < 4; j++) {
                uint2 b = pb[j * 8 + g];
                unsigned bb[2] = {b.x, b.y};
#pragma unroll
                for (int i = 0; i < 2; i++) {
                    unsigned aa[4] = {a0[i].x, a1[i].x, a0[i].y, a1[i].y};
                    mma_tf32(acc[i][j], aa, bb);
                }
            }
        }
        if (s + 1 < NS) sts_stage((s + 1) & 1);
        __syncthreads();
    }

    // epilogue: out[token] += gate * y (exactly 2 contributions per element -> deterministic)
#pragma unroll
    for (int i = 0; i < 2; i++) {
        int rb0 = mw + i * 16 + g;
#pragma unroll
        for (int j = 0; j < 4; j++) {
            int c = nw + j * 8 + tg * 2;
            if (rb0 < rows) {
                int tk = s_tok[rb0];
                float gg = s_g[rb0];
                atomicAdd(&out[(size_t)tk * HID + n0 + c], gg * acc[i][j][0]);
                atomicAdd(&out[(size_t)tk * HID + n0 + c + 1], gg * acc[i][j][1]);
            }
            int rb2 = rb0 + 8;
            if (rb2 < rows) {
                int tk = s_tok[rb2];
                float gg = s_g[rb2];
                atomicAdd(&out[(size_t)tk * HID + n0 + c], gg * acc[i][j][2]);
                atomicAdd(&out[(size_t)tk * HID + n0 + c + 1], gg * acc[i][j][3]);
            }
        }
    }
}

// ---------------- launch ----------------
extern "C" void kernel_launch(void* const* d_in, const int* in_sizes, int n_in,
                              void* d_out, int out_size) {
    const float* hs  = (const float*)d_in[0];  // hidden_states [2,2048,1024]
    const float* lnw = (const float*)d_in[1];  // ln_weight [1024]
    const float* rw  = (const float*)d_in[2];  // router_w [1024,8]
    const float* w1  = (const float*)d_in[3];  // [8,1024,2816]
    const float* w3  = (const float*)d_in[4];  // [8,1024,2816]
    const float* w2  = (const float*)d_in[5];  // [8,2816,1024]
    float* out = (float*)d_out;                // [2,2048,1024] fp32

    k_zero<<<2048, 256>>>(out, out_size);
    k_rms_router<<<T_TOK, 128>>>(hs, lnw, rw);
    k_route<<<1, 256>>>();
    dim3 g1(FFN / BN, MT_MAX);
    k_gemm1<<<g1, 256>>>(w1, w3);
    dim3 g2(HID / BN, MT_MAX);
    k_gemm2<<<g2, 256>>>(w2, out);
}

// round 17
// speedup vs baseline: 1.5166x; 1.2969x over previous
#include <cuda_runtime.h>
#include <stdint.h>
#include <math.h>

#define T_TOK 4096
#define HID   1024
#define FFN   2816
#define NE    8
#define RMAX  8192
#define BM    128
#define BN    128
#define BK    16
#define MT_MAX 72

// smem geometry (bytes)
#define AROW 80            // 16 floats + 16B pad  (banks 20g+tg: conflict-free)
#define BROW 544           // 128 floats + 32B pad (banks 8tg+g: conflict-free)
#define ABUF (BM*AROW)     // 10240
#define BBUF (BK*BROW)     // 8704
#define STG1 (ABUF+2*BBUF) // 27648 (gemm1 stage: A,B1,B3)
#define STG2 (ABUF+BBUF)   // 18944 (gemm2 stage)

__device__ float g_xn[T_TOK * HID];     // tf32-rounded normalized activations
__device__ float g_act[RMAX * FFN];     // tf32-rounded SwiGLU activations
__device__ float g_w1r[NE * HID * FFN]; // tf32-rounded weights
__device__ float g_w3r[NE * HID * FFN];
__device__ float g_w2r[NE * FFN * HID];
__device__ int   g_counts[NE];
__device__ int   g_perm[RMAX];
__device__ float g_gate[RMAX];
__device__ int   g_topi[T_TOK * 2];
__device__ float g_topp[T_TOK * 2];
__device__ int   g_tile_e[MT_MAX];
__device__ int   g_tile_row0[MT_MAX];
__device__ int   g_tile_rows[MT_MAX];
__device__ int   g_nmt;

__device__ __forceinline__ unsigned f2tf(float x){unsigned u;asm("cvt.rna.tf32.f32 %0,%1;":"=r"(u):"f"(x));return u;}
__device__ __forceinline__ uint32_t s2u(const void* p){uint32_t a;asm("{.reg .u64 t; cvta.to.shared.u64 t,%1; cvt.u32.u64 %0,t;}":"=r"(a):"l"(p));return a;}
__device__ __forceinline__ void cpa(uint32_t dst,const void* src,unsigned sz){
    asm volatile("cp.async.ca.shared.global [%0], [%1], 16, %2;"::"r"(dst),"l"(src),"r"(sz):"memory");
}
__device__ __forceinline__ void cp_commit(){ asm volatile("cp.async.commit_group;":::"memory"); }
__device__ __forceinline__ void cp_wait2(){ asm volatile("cp.async.wait_group 2;":::"memory"); }
__device__ __forceinline__ void mma_tf32(float c[4],const unsigned a[4],const unsigned b[2]){
    asm volatile("mma.sync.aligned.m16n8k8.row.col.f32.tf32.tf32.f32 "
        "{%0,%1,%2,%3}, {%4,%5,%6,%7}, {%8,%9}, {%0,%1,%2,%3};"
        : "+f"(c[0]),"+f"(c[1]),"+f"(c[2]),"+f"(c[3])
        : "r"(a[0]),"r"(a[1]),"r"(a[2]),"r"(a[3]),"r"(b[0]),"r"(b[1]));
}

__global__ void k_zero(float* __restrict__ out,int n){
    int gi=blockIdx.x*blockDim.x+threadIdx.x;
    for(int i=gi;i<n;i+=gridDim.x*blockDim.x) out[i]=0.0f;
    if(gi<NE) g_counts[gi]=0;
}

// round fp32 -> tf32-in-fp32 (RNA), float4 grid-stride
__global__ void k_round(const float4* __restrict__ s,float4* __restrict__ d,int n4){
    int gi=blockIdx.x*blockDim.x+threadIdx.x;
    for(int i=gi;i<n4;i+=gridDim.x*blockDim.x){
        float4 v=s[i];
        d[i]=make_float4(__uint_as_float(f2tf(v.x)),__uint_as_float(f2tf(v.y)),
                         __uint_as_float(f2tf(v.z)),__uint_as_float(f2tf(v.w)));
    }
}

__global__ void k_rms_router(const float* __restrict__ x,const float* __restrict__ lnw,const float* __restrict__ rw){
    int t=blockIdx.x,tid=threadIdx.x,lane=tid&31,w=tid>>5,h0=tid*8;
    const float* xr=x+(size_t)t*HID;
    float4 v0=*(const float4*)(xr+h0),v1=*(const float4*)(xr+h0+4);
    float ss=v0.x*v0.x+v0.y*v0.y+v0.z*v0.z+v0.w*v0.w+v1.x*v1.x+v1.y*v1.y+v1.z*v1.z+v1.w*v1.w;
#pragma unroll
    for(int o=16;o;o>>=1) ss+=__shfl_xor_sync(0xffffffffu,ss,o);
    __shared__ float s_red[4],s_l[4][8],s_rstd;
    if(lane==0) s_red[w]=ss;
    __syncthreads();
    if(tid==0) s_rstd=rsqrtf((s_red[0]+s_red[1]+s_red[2]+s_red[3])/(float)HID+1e-5f);
    __syncthreads();
    float rstd=s_rstd;
    float4 wa=*(const float4*)(lnw+h0),wb=*(const float4*)(lnw+h0+4);
    float xn[8]={v0.x*rstd*wa.x,v0.y*rstd*wa.y,v0.z*rstd*wa.z,v0.w*rstd*wa.w,
                 v1.x*rstd*wb.x,v1.y*rstd*wb.y,v1.z*rstd*wb.z,v1.w*rstd*wb.w};
    float* gx=g_xn+(size_t)t*HID+h0;
#pragma unroll
    for(int j=0;j<8;j++) gx[j]=__uint_as_float(f2tf(xn[j]));
    float l[8]={0,0,0,0,0,0,0,0};
#pragma unroll
    for(int j=0;j<8;j++){
        const float4* rp=(const float4*)(rw+(size_t)(h0+j)*NE);
        float4 r0=rp[0],r1=rp[1];float xv=xn[j];
        l[0]+=xv*r0.x;l[1]+=xv*r0.y;l[2]+=xv*r0.z;l[3]+=xv*r0.w;
        l[4]+=xv*r1.x;l[5]+=xv*r1.y;l[6]+=xv*r1.z;l[7]+=xv*r1.w;
    }
#pragma unroll
    for(int o=16;o;o>>=1){
#pragma unroll
        for(int e=0;e<8;e++) l[e]+=__shfl_xor_sync(0xffffffffu,l[e],o);
    }
    if(lane==0){
#pragma unroll
        for(int e=0;e<8;e++) s_l[w][e]=l[e];
    }
    __syncthreads();
    if(tid==0){
        float lg[8];
#pragma unroll
        for(int e=0;e<8;e++) lg[e]=s_l[0][e]+s_l[1][e]+s_l[2][e]+s_l[3][e];
        float mx=lg[0];
#pragma unroll
        for(int e=1;e<8;e++) mx=fmaxf(mx,lg[e]);
        float p[8],se=0.0f;
#pragma unroll
        for(int e=0;e<8;e++){p[e]=expf(lg[e]-mx);se+=p[e];}
        float inv=1.0f/se;int i1=0;
#pragma unroll
        for(int e=1;e<8;e++) if(p[e]>p[i1]) i1=e;
        int i2=-1;
#pragma unroll
        for(int e=0;e<8;e++) if(e!=i1&&(i2<0||p[e]>p[i2])) i2=e;
        g_topi[2*t+0]=i1;g_topp[2*t+0]=p[i1]*inv;
        g_topi[2*t+1]=i2;g_topp[2*t+1]=p[i2]*inv;
        atomicAdd(&g_counts[i1],1);atomicAdd(&g_counts[i2],1);
    }
}

__global__ void k_route(){
    __shared__ int s_cur[NE];
    int tid=threadIdx.x;
    if(tid==0){
        int off=0,nm=0;
        for(int e=0;e<NE;e++){
            s_cur[e]=off;int n=g_counts[e];
            for(int m0=0;m0<n;m0+=BM){
                g_tile_e[nm]=e;g_tile_row0[nm]=off+m0;g_tile_rows[nm]=min(BM,n-m0);nm++;
            }
            off+=n;
        }
        g_nmt=nm;
    }
    __syncthreads();
    for(int t=tid;t<T_TOK;t+=blockDim.x){
        for(int k=0;k<2;k++){
            int e=g_topi[2*t+k];
            int pos=atomicAdd(&s_cur[e],1);
            g_perm[pos]=t;g_gate[pos]=g_topp[2*t+k];
        }
    }
}

// ---- GEMM1: 512 thr, BM=128 BN=128, warps 4m x 4n (32x32), cp.async 3-stage ----
__global__ __launch_bounds__(512,1) void k_gemm1(){
    extern __shared__ char sm[];
    __shared__ int s_tok[BM];
    int mt=blockIdx.y; if(mt>=g_nmt) return;
    int e=g_tile_e[mt],row0=g_tile_row0[mt],rows=g_tile_rows[mt];
    int n0=blockIdx.x*BN;
    int tid=threadIdx.x,wz=tid>>5,lane=tid&31;
    if(tid<BM) s_tok[tid]=(tid<rows)?g_perm[row0+tid]:-1;
    __syncthreads();
    uint32_t smu=s2u(sm);

    // A loader: 1 chunk/thread (row tid>>2, 16B chunk tid&3)
    int arow=tid>>2, ach=tid&3;
    int atok=s_tok[arow];
    const char* asrc=(const char*)g_xn + (size_t)(atok<0?0:atok)*HID*4 + (size_t)ach*16;
    unsigned asz=(atok>=0)?16u:0u;
    uint32_t adst=smu + arow*AROW + ach*16;

    // B loader: 2 chunks/thread (matrix tid>>8, k-row (tid>>4)&15, chunks tid&15 and +16)
    int bmat=tid>>8, brow=(tid>>4)&15, bch=tid&15;
    const float* wr=bmat? g_w3r : g_w1r;
    const char* bsrc=(const char*)(wr + (size_t)e*HID*FFN + (size_t)brow*FFN + n0) + (size_t)bch*16;
    uint32_t bdst=smu + ABUF + bmat*BBUF + brow*BROW + bch*16;

    auto issue=[&](int c){
        uint32_t bb=(uint32_t)(c%3)*STG1;
        cpa(adst+bb, asrc+(size_t)c*64, asz);
        const char* bs=bsrc+(size_t)c*(BK*(size_t)FFN*4);
        cpa(bdst+bb, bs, 16u);
        cpa(bdst+bb+256, bs+256, 16u);
    };

    int mw=(wz&3)*32, nw=(wz>>2)*32;
    int g=lane>>2, tg=lane&3;
    float acc1[2][4][4]={}, acc3[2][4][4]={};

    issue(0); cp_commit();
    issue(1); cp_commit();

    const int NS=HID/BK; // 64
    for(int s=0;s<NS;s++){
        if(s+2<NS) issue(s+2);
        cp_commit();
        cp_wait2();
        __syncthreads();
        const char* Ab=sm+(s%3)*STG1;
        const char* B1=Ab+ABUF;
        const char* B3=B1+BBUF;
#pragma unroll
        for(int kk=0;kk<BK;kk+=8){
            unsigned a[2][4],b1[4][2],b3[4][2];
#pragma unroll
            for(int i=0;i<2;i++){
                const char* r0=Ab+(mw+i*16+g)*AROW;
                const char* r8=Ab+(mw+i*16+g+8)*AROW;
                a[i][0]=*(const unsigned*)(r0+(kk+tg)*4);
                a[i][1]=*(const unsigned*)(r8+(kk+tg)*4);
                a[i][2]=*(const unsigned*)(r0+(kk+tg+4)*4);
                a[i][3]=*(const unsigned*)(r8+(kk+tg+4)*4);
            }
#pragma unroll
            for(int j=0;j<4;j++){
                int nn=(nw+j*8+g)*4;
                b1[j][0]=*(const unsigned*)(B1+(kk+tg)*BROW+nn);
                b1[j][1]=*(const unsigned*)(B1+(kk+tg+4)*BROW+nn);
                b3[j][0]=*(const unsigned*)(B3+(kk+tg)*BROW+nn);
                b3[j][1]=*(const unsigned*)(B3+(kk+tg+4)*BROW+nn);
            }
#pragma unroll
            for(int i=0;i<2;i++)
#pragma unroll
                for(int j=0;j<4;j++){
                    mma_tf32(acc1[i][j],a[i],b1[j]);
                    mma_tf32(acc3[i][j],a[i],b3[j]);
                }
        }
        __syncthreads();
    }

    // epilogue: act = silu(h1)*h3, rounded to tf32
#pragma unroll
    for(int i=0;i<2;i++){
        int rb=mw+i*16+g;
#pragma unroll
        for(int j=0;j<4;j++){
            int c=nw+j*8+tg*2;
            if(rb<rows){
                float h1a=acc1[i][j][0],h1b=acc1[i][j][1];
                float h3a=acc3[i][j][0],h3b=acc3[i][j][1];
                float sa=h1a/(1.0f+__expf(-h1a)),sb=h1b/(1.0f+__expf(-h1b));
                *(float2*)(g_act+(size_t)(row0+rb)*FFN+n0+c)=
                    make_float2(__uint_as_float(f2tf(sa*h3a)),__uint_as_float(f2tf(sb*h3b)));
            }
            int rb2=rb+8;
            if(rb2<rows){
                float h1a=acc1[i][j][2],h1b=acc1[i][j][3];
                float h3a=acc3[i][j][2],h3b=acc3[i][j][3];
                float sa=h1a/(1.0f+__expf(-h1a)),sb=h1b/(1.0f+__expf(-h1b));
                *(float2*)(g_act+(size_t)(row0+rb2)*FFN+n0+c)=
                    make_float2(__uint_as_float(f2tf(sa*h3a)),__uint_as_float(f2tf(sb*h3b)));
            }
        }
    }
}

// ---- GEMM2: 512 thr, BM=128 BN=128, warps 4m x 4n (32x32), cp.async 3-stage ----
__global__ __launch_bounds__(512,1) void k_gemm2(float* __restrict__ out){
    extern __shared__ char sm[];
    __shared__ int s_tok[BM];
    __shared__ float s_g[BM];
    int mt=blockIdx.y; if(mt>=g_nmt) return;
    int e=g_tile_e[mt],row0=g_tile_row0[mt],rows=g_tile_rows[mt];
    int n0=blockIdx.x*BN;
    int tid=threadIdx.x,wz=tid>>5,lane=tid&31;
    if(tid<BM){bool v=tid<rows; s_tok[tid]=v?g_perm[row0+tid]:-1; s_g[tid]=v?g_gate[row0+tid]:0.0f;}
    __syncthreads();
    uint32_t smu=s2u(sm);

    int arow=tid>>2, ach=tid&3;
    bool av=arow<rows;
    const char* asrc=(const char*)g_act + (size_t)(row0+(av?arow:0))*FFN*4 + (size_t)ach*16;
    unsigned asz=av?16u:0u;
    uint32_t adst=smu + arow*AROW + ach*16;

    int brow=tid>>5, bch=tid&31;   // 16 rows x 32 chunks = 512
    const char* bsrc=(const char*)(g_w2r + (size_t)e*FFN*HID + (size_t)brow*HID + n0) + (size_t)bch*16;
    uint32_t bdst=smu + ABUF + brow*BROW + bch*16;

    auto issue=[&](int c){
        uint32_t bb=(uint32_t)(c%3)*STG2;
        cpa(adst+bb, asrc+(size_t)c*64, asz);
        cpa(bdst+bb, bsrc+(size_t)c*(BK*(size_t)HID*4), 16u);
    };

    int mw=(wz&3)*32, nw=(wz>>2)*32;
    int g=lane>>2, tg=lane&3;
    float acc[2][4][4]={};

    issue(0); cp_commit();
    issue(1); cp_commit();

    const int NS=FFN/BK; // 176
    for(int s=0;s<NS;s++){
        if(s+2<NS) issue(s+2);
        cp_commit();
        cp_wait2();
        __syncthreads();
        const char* Ab=sm+(s%3)*STG2;
        const char* Bb=Ab+ABUF;
#pragma unroll
        for(int kk=0;kk<BK;kk+=8){
            unsigned a[2][4],b[4][2];
#pragma unroll
            for(int i=0;i<2;i++){
                const char* r0=Ab+(mw+i*16+g)*AROW;
                const char* r8=Ab+(mw+i*16+g+8)*AROW;
                a[i][0]=*(const unsigned*)(r0+(kk+tg)*4);
                a[i][1]=*(const unsigned*)(r8+(kk+tg)*4);
                a[i][2]=*(const unsigned*)(r0+(kk+tg+4)*4);
                a[i][3]=*(const unsigned*)(r8+(kk+tg+4)*4);
            }
#pragma unroll
            for(int j=0;j<4;j++){
                int nn=(nw+j*8+g)*4;
                b[j][0]=*(const unsigned*)(Bb+(kk+tg)*BROW+nn);
                b[j][1]=*(const unsigned*)(Bb+(kk+tg+4)*BROW+nn);
            }
#pragma unroll
            for(int i=0;i<2;i++)
#pragma unroll
                for(int j=0;j<4;j++) mma_tf32(acc[i][j],a[i],b[j]);
        }
        __syncthreads();
    }

#pragma unroll
    for(int i=0;i<2;i++){
        int rb=mw+i*16+g;
#pragma unroll
        for(int j=0;j<4;j++){
            int c=nw+j*8+tg*2;
            if(rb<rows){
                int tk=s_tok[rb]; float gg=s_g[rb];
                atomicAdd(&out[(size_t)tk*HID+n0+c],  gg*acc[i][j][0]);
                atomicAdd(&out[(size_t)tk*HID+n0+c+1],gg*acc[i][j][1]);
            }
            int rb2=rb+8;
            if(rb2<rows){
                int tk=s_tok[rb2]; float gg=s_g[rb2];
                atomicAdd(&out[(size_t)tk*HID+n0+c],  gg*acc[i][j][2]);
                atomicAdd(&out[(size_t)tk*HID+n0+c+1],gg*acc[i][j][3]);
            }
        }
    }
}

extern "C" void kernel_launch(void* const* d_in,const int* in_sizes,int n_in,void* d_out,int out_size){
    const float* hs =(const float*)d_in[0];
    const float* lnw=(const float*)d_in[1];
    const float* rw =(const float*)d_in[2];
    const float* w1 =(const float*)d_in[3];
    const float* w3 =(const float*)d_in[4];
    const float* w2 =(const float*)d_in[5];
    float* out=(float*)d_out;

    cudaFuncSetAttribute(k_gemm1,cudaFuncAttributeMaxDynamicSharedMemorySize,3*STG1);
    cudaFuncSetAttribute(k_gemm2,cudaFuncAttributeMaxDynamicSharedMemorySize,3*STG2);

    float* w1r; cudaGetSymbolAddress((void**)&w1r,g_w1r);
    float* w3r; cudaGetSymbolAddress((void**)&w3r,g_w3r);
    float* w2r; cudaGetSymbolAddress((void**)&w2r,g_w2r);

    const int N4=NE*HID*FFN/4;
    k_zero<<<2048,256>>>(out,out_size);
    k_round<<<4096,256>>>((const float4*)w1,(float4*)w1r,N4);
    k_round<<<4096,256>>>((const float4*)w3,(float4*)w3r,N4);
    k_round<<<4096,256>>>((const float4*)w2,(float4*)w2r,N4);
    k_rms_router<<<T_TOK,128>>>(hs,lnw,rw);
    k_route<<<1,256>>>();
    k_gemm1<<<dim3(FFN/BN,MT_MAX),512,3*STG1>>>();
    k_gemm2<<<dim3(HID/BN,MT_MAX),512,3*STG2>>>(out);
}